// round 1
// baseline (speedup 1.0000x reference)
#include <cuda_runtime.h>
#include <cstdint>

#define N_BOX    2048
#define R_OUT    100
#define NTHREADS 1024

// Shared memory layout (dynamic, 43408 bytes):
//   [0,16384)      : u64 keys[2048]        (sort phase only; aliased below)
//   [0,8192)       : float sl[2048]        (after sort)
//   [8192,16384)   : float st[2048]
//   [16384,24576)  : float sr[2048]
//   [24576,32768)  : float sb[2048]
//   [32768,40960)  : float area[2048]
//   [40960,43008)  : u8   keep[2048]
//   [43008,43408)  : int  kidx[100]
#define SMEM_BYTES 43408

__global__ __launch_bounds__(NTHREADS, 1)
void nms_kernel(const float* __restrict__ pred, float* __restrict__ out) {
    const int b   = blockIdx.x;
    const int tid = threadIdx.x;
    const float* p = pred + (size_t)b * N_BOX * 5;

    extern __shared__ unsigned char smem[];
    unsigned long long* keys = (unsigned long long*)smem;
    float* sl    = (float*)(smem);
    float* st    = (float*)(smem + 8192);
    float* sr    = (float*)(smem + 16384);
    float* sb    = (float*)(smem + 24576);
    float* sarea = (float*)(smem + 32768);
    unsigned char* keep = smem + 40960;
    int*  kidx   = (int*)(smem + 43008);
    __shared__ int s_kept;

    // ---- Phase 1: build sort keys (score desc, index asc tie-break = stable argsort(-s))
    // scores are in [0,1) (non-negative) -> raw float bits are order-preserving.
    for (int n = tid; n < N_BOX; n += NTHREADS) {
        unsigned int sbits = __float_as_uint(p[n * 5 + 0]);
        keys[n] = ((unsigned long long)sbits << 32) | (0xFFFFFFFFu - (unsigned)n);
    }
    __syncthreads();

    // ---- Phase 2: bitonic sort, descending, 2048 elements / 1024 threads
    for (int k = 2; k <= N_BOX; k <<= 1) {
        for (int j = k >> 1; j > 0; j >>= 1) {
            #pragma unroll
            for (int w = 0; w < 2; ++w) {
                int t = tid + w * NTHREADS;
                int ixj = t ^ j;
                if (ixj > t) {
                    unsigned long long a = keys[t], c = keys[ixj];
                    bool dir = ((t & k) == 0);        // descending segments
                    if ((a < c) == dir) { keys[t] = c; keys[ixj] = a; }
                }
            }
            __syncthreads();
        }
    }

    // ---- Phase 3: pull sorted indices into registers, then gather boxes
    // (keys buffer is aliased by sl/st, so stage through registers + barrier)
    unsigned idx0 = 0xFFFFFFFFu - (unsigned)(keys[tid]            & 0xFFFFFFFFu);
    unsigned idx1 = 0xFFFFFFFFu - (unsigned)(keys[tid + NTHREADS] & 0xFFFFFFFFu);
    __syncthreads();
    {
        const float* q = p + (size_t)idx0 * 5;
        float l = q[1], t = q[2], r = q[3], bo = q[4];
        sl[tid] = l; st[tid] = t; sr[tid] = r; sb[tid] = bo;
        sarea[tid] = (r - l) * (bo - t);
        keep[tid] = 1;

        q = p + (size_t)idx1 * 5;
        l = q[1]; t = q[2]; r = q[3]; bo = q[4];
        int n = tid + NTHREADS;
        sl[n] = l; st[n] = t; sr[n] = r; sb[n] = bo;
        sarea[n] = (r - l) * (bo - t);
        keep[n] = 1;
    }
    if (tid == 0) s_kept = 0;
    __syncthreads();

    // ---- Phase 4: greedy sequential suppression with early exit at R kept.
    // Only the first R kept boxes reach the output, and suppression by box i
    // only matters for j > i, so stopping once s_kept == R is exact.
    for (int i = 0; i < N_BOX; ++i) {
        if (s_kept >= R_OUT) break;               // uniform (barrier'd shared read)
        if (keep[i]) {
            float li = sl[i], ti = st[i], ri = sr[i], bi = sb[i];
            for (int j = i + 1 + tid; j < N_BOX; j += NTHREADS) {
                float iw = fminf(ri, sr[j]) - fmaxf(li, sl[j]);
                float ih = fminf(bi, sb[j]) - fmaxf(ti, st[j]);
                float inter = fmaxf(iw, 0.0f) * fmaxf(ih, 0.0f);
                float ov = __fdiv_rn(inter, sarea[j]);  // IEEE RN: match reference exactly
                if (!(ov < 0.5f)) keep[j] = 0;
            }
            if (tid == 0) { kidx[s_kept] = i; s_kept = s_kept + 1; }
        }
        __syncthreads();
    }
    __syncthreads();

    // ---- Phase 5: write output: (top, right, bottom) per kept slot, zeros after
    int nk = s_kept; if (nk > R_OUT) nk = R_OUT;
    float* ob = out + (size_t)b * R_OUT * 3;
    for (int s = tid; s < R_OUT; s += NTHREADS) {
        if (s < nk) {
            int i = kidx[s];
            ob[s * 3 + 0] = st[i];
            ob[s * 3 + 1] = sr[i];
            ob[s * 3 + 2] = sb[i];
        } else {
            ob[s * 3 + 0] = 0.0f;
            ob[s * 3 + 1] = 0.0f;
            ob[s * 3 + 2] = 0.0f;
        }
    }
}

extern "C" void kernel_launch(void* const* d_in, const int* in_sizes, int n_in,
                              void* d_out, int out_size) {
    const float* pred = (const float*)d_in[0];
    float* out = (float*)d_out;
    (void)in_sizes; (void)n_in; (void)out_size;
    nms_kernel<<<32, NTHREADS, SMEM_BYTES>>>(pred, out);
}

// round 2
// speedup vs baseline: 2.0000x; 2.0000x over previous
#include <cuda_runtime.h>
#include <cstdint>

#define N_BOX    2048
#define R_OUT    100
#define NTHREADS 1024

typedef unsigned long long u64;
typedef unsigned int u32;

// Shared memory layout (dynamic):
//   sort phase: bufA u64[2048] @0 (16KB), bufB u64[2048] @16384 (16KB)
//   post-sort SoA (aliases sort buffers):
//     sl   f32[2048] @0
//     st   f32[2048] @8192
//     sr   f32[2048] @16384
//     sb   f32[2048] @24576
//     sha  f32[2048] @32768   (0.5f * area)
//     keep u8 [2048] @40960
//     mask u32[32]   @43008
//     kidx int[100]  @43136
#define SMEM_BYTES (43136 + 400)

__device__ __forceinline__ void cmpex(u64& v, u64 u, bool lower, bool desc) {
    // element keeps max if it is the lower index of a descending pair (or upper of ascending)
    bool takeMax = (lower == desc);
    if (takeMax ? (u > v) : (u < v)) v = u;
}

__global__ __launch_bounds__(NTHREADS, 1)
void nms_kernel(const float* __restrict__ pred, float* __restrict__ out) {
    const int b    = blockIdx.x;
    const int tid  = threadIdx.x;
    const int lane = tid & 31;
    const int w    = tid >> 5;
    const float* p = pred + (size_t)b * N_BOX * 5;

    extern __shared__ unsigned char smem[];
    u64*  bufA = (u64*)smem;
    u64*  bufB = (u64*)(smem + 16384);
    float* sl   = (float*)(smem);
    float* st   = (float*)(smem + 8192);
    float* sr   = (float*)(smem + 16384);
    float* sb   = (float*)(smem + 24576);
    float* sha  = (float*)(smem + 32768);
    unsigned char* keep = smem + 40960;
    u32*  smask = (u32*)(smem + 43008);
    int*  kidx  = (int*)(smem + 43136);
    __shared__ int s_kept;
    __shared__ u32 s_keptbits;
    __shared__ int s_stop;

    const int e0 = w * 64 + lane;
    const int e1 = e0 + 32;

    // ---- Phase 1: keys in registers. (score desc, index asc tiebreak)
    // scores in [0,1) -> raw bits order-preserving for non-negative floats.
    u64 v0 = (((u64)__float_as_uint(p[e0 * 5])) << 32) | (u64)(0xFFFFFFFFu - (u32)e0);
    u64 v1 = (((u64)__float_as_uint(p[e1 * 5])) << 32) | (u64)(0xFFFFFFFFu - (u32)e1);

    // ---- Phase 2: bitonic sort (descending). shfl for j<=16, reg-swap for j=32,
    // smem ping-pong for j>=64 (one barrier per smem stage).
    int bufsel = 0;
    for (int k = 2; k <= N_BOX; k <<= 1) {
        for (int j = k >> 1; j >= 64; j >>= 1) {
            u64* buf = bufsel ? bufB : bufA;
            buf[e0] = v0; buf[e1] = v1;
            __syncthreads();
            u64 u0 = buf[e0 ^ j];
            u64 u1 = buf[e1 ^ j];
            cmpex(v0, u0, (e0 & j) == 0, (e0 & k) == 0);
            cmpex(v1, u1, (e1 & j) == 0, (e1 & k) == 0);
            bufsel ^= 1;
        }
        if (k >= 64) {
            // j = 32: pair is (e0, e1) within this thread; e0 is the lower index.
            bool desc = ((e0 & k) == 0);
            if (desc ? (v0 < v1) : (v0 > v1)) { u64 t = v0; v0 = v1; v1 = t; }
        }
        int jstart = (k >> 1) < 16 ? (k >> 1) : 16;
        for (int j = jstart; j >= 1; j >>= 1) {
            u64 u0 = __shfl_xor_sync(0xFFFFFFFFu, v0, j);
            u64 u1 = __shfl_xor_sync(0xFFFFFFFFu, v1, j);
            bool lower = (lane & j) == 0;
            cmpex(v0, u0, lower, (e0 & k) == 0);
            cmpex(v1, u1, lower, (e1 & k) == 0);
        }
    }
    __syncthreads();   // all smem key reads done before SoA overwrite

    // ---- Phase 3: gather boxes into SoA by sorted rank
    {
        u32 i0 = 0xFFFFFFFFu - (u32)(v0 & 0xFFFFFFFFu);
        u32 i1 = 0xFFFFFFFFu - (u32)(v1 & 0xFFFFFFFFu);
        const float* q = p + (size_t)i0 * 5;
        float l = q[1], t = q[2], r = q[3], bo = q[4];
        sl[e0] = l; st[e0] = t; sr[e0] = r; sb[e0] = bo;
        sha[e0] = 0.5f * ((r - l) * (bo - t));
        keep[e0] = 1;
        q = p + (size_t)i1 * 5;
        l = q[1]; t = q[2]; r = q[3]; bo = q[4];
        sl[e1] = l; st[e1] = t; sr[e1] = r; sb[e1] = bo;
        sha[e1] = 0.5f * ((r - l) * (bo - t));
        keep[e1] = 1;
    }
    if (tid == 0) { s_kept = 0; s_stop = 0; }
    __syncthreads();

    // ---- Phase 4: chunked greedy suppression (exactly equivalent to the
    // sequential greedy; suppress iff inter >= 0.5*area_j).
    for (int base = 0; base < N_BOX; base += 32) {
        // 32x32 suppression matrix: warp w = column (base+w), lane = row (base+lane)
        {
            int bc = base + w;
            float lb = sl[bc], tb = st[bc], rb = sr[bc], bb = sb[bc], hb = sha[bc];
            int ar = base + lane;
            float iw = fminf(rb, sr[ar]) - fmaxf(lb, sl[ar]);
            float ih = fminf(bb, sb[ar]) - fmaxf(tb, st[ar]);
            float inter = fmaxf(iw, 0.0f) * fmaxf(ih, 0.0f);
            u32 m = __ballot_sync(0xFFFFFFFFu, inter >= hb);
            if (lane == 0) smask[w] = m;
        }
        __syncthreads();
        if (tid == 0) {
            u32 kb = 0;
            int cnt = s_kept;
            #pragma unroll 1
            for (int a = 0; a < 32; ++a) {
                if (keep[base + a] && ((smask[a] & kb) == 0)) {
                    kb |= (1u << a);
                    if (cnt < R_OUT) kidx[cnt] = base + a;
                    cnt++;
                }
            }
            s_keptbits = kb;
            s_kept = cnt;
            s_stop = (cnt >= R_OUT);
        }
        __syncthreads();
        if (s_stop) break;
        u32 kb = s_keptbits;
        // downstream suppression by this chunk's kept set
        for (int jj = base + 32 + tid; jj < N_BOX; jj += NTHREADS) {
            if (!keep[jj]) continue;
            float lj = sl[jj], tj = st[jj], rj = sr[jj], bj = sb[jj], hj = sha[jj];
            u32 m2 = kb;
            bool sup = false;
            while (m2) {
                int a = __ffs(m2) - 1;
                m2 &= m2 - 1;
                int ii = base + a;
                float iw2 = fminf(sr[ii], rj) - fmaxf(sl[ii], lj);
                float ih2 = fminf(sb[ii], bj) - fmaxf(st[ii], tj);
                float in2 = fmaxf(iw2, 0.0f) * fmaxf(ih2, 0.0f);
                if (in2 >= hj) { sup = true; break; }
            }
            if (sup) keep[jj] = 0;
        }
        __syncthreads();
    }
    __syncthreads();

    // ---- Phase 5: output (top, right, bottom) for first R kept, zeros after
    int nk = s_kept; if (nk > R_OUT) nk = R_OUT;
    float* ob = out + (size_t)b * R_OUT * 3;
    if (tid < R_OUT) {
        int s = tid;
        if (s < nk) {
            int i = kidx[s];
            ob[s * 3 + 0] = st[i];
            ob[s * 3 + 1] = sr[i];
            ob[s * 3 + 2] = sb[i];
        } else {
            ob[s * 3 + 0] = 0.0f;
            ob[s * 3 + 1] = 0.0f;
            ob[s * 3 + 2] = 0.0f;
        }
    }
}

extern "C" void kernel_launch(void* const* d_in, const int* in_sizes, int n_in,
                              void* d_out, int out_size) {
    const float* pred = (const float*)d_in[0];
    float* out = (float*)d_out;
    (void)in_sizes; (void)n_in; (void)out_size;
    nms_kernel<<<32, NTHREADS, SMEM_BYTES>>>(pred, out);
}

// round 3
// speedup vs baseline: 3.5020x; 1.7510x over previous
#include <cuda_runtime.h>
#include <cstdint>

#define N_BOX    2048
#define R_OUT    100
#define NTHREADS 1024
#define KMAX     160

typedef unsigned long long u64;
typedef unsigned int u32;

// Shared memory layout (dynamic, 44176 bytes):
//   sort: bufA u64[2048] @0, bufB u64[2048] @16384   (aliased by SoA below)
//   sl   f32[2048] @0       st f32[2048] @8192
//   sr   f32[2048] @16384   sb f32[2048] @24576
//   sha  f32[2048] @32768   (0.5f * area)
//   kL/kT/kR/kB2 f32[160] @40960/41600/42240/42880   (compact kept list)
//   smask  u32[32] @43520   sprior u32[32] @43648
//   kidx   int[100] @43776
#define SMEM_BYTES 44176

__device__ __forceinline__ void cmpex(u64& v, u64 u, bool lower, bool desc) {
    bool takeMax = (lower == desc);
    if (takeMax ? (u > v) : (u < v)) v = u;
}

__global__ __launch_bounds__(NTHREADS, 1)
void nms_kernel(const float* __restrict__ pred, float* __restrict__ out) {
    const int b    = blockIdx.x;
    const int tid  = threadIdx.x;
    const int lane = tid & 31;
    const int w    = tid >> 5;
    const float* p = pred + (size_t)b * N_BOX * 5;

    extern __shared__ unsigned char smem[];
    u64*  bufA = (u64*)smem;
    u64*  bufB = (u64*)(smem + 16384);
    float* sl   = (float*)(smem);
    float* st   = (float*)(smem + 8192);
    float* sr   = (float*)(smem + 16384);
    float* sb   = (float*)(smem + 24576);
    float* sha  = (float*)(smem + 32768);
    float* kL   = (float*)(smem + 40960);
    float* kT   = (float*)(smem + 41600);
    float* kR   = (float*)(smem + 42240);
    float* kB2  = (float*)(smem + 42880);
    u32*  smask  = (u32*)(smem + 43520);
    u32*  sprior = (u32*)(smem + 43648);
    int*  kidx   = (int*)(smem + 43776);
    __shared__ int s_kept;     // total kept (greedy count)
    __shared__ int s_nkept;    // size of compact kept list
    __shared__ int s_stop;

    const int e0 = w * 64 + lane;
    const int e1 = e0 + 32;

    // ---- Phase 1: keys in registers (score desc, index asc tiebreak).
    // scores in [0,1) -> raw float bits are order-preserving.
    u64 v0 = (((u64)__float_as_uint(p[e0 * 5])) << 32) | (u64)(0xFFFFFFFFu - (u32)e0);
    u64 v1 = (((u64)__float_as_uint(p[e1 * 5])) << 32) | (u64)(0xFFFFFFFFu - (u32)e1);

    // ---- Phase 2: bitonic sort (descending): shfl j<=16, reg-swap j=32, smem j>=64
    int bufsel = 0;
    for (int k = 2; k <= N_BOX; k <<= 1) {
        for (int j = k >> 1; j >= 64; j >>= 1) {
            u64* buf = bufsel ? bufB : bufA;
            buf[e0] = v0; buf[e1] = v1;
            __syncthreads();
            u64 u0 = buf[e0 ^ j];
            u64 u1 = buf[e1 ^ j];
            cmpex(v0, u0, (e0 & j) == 0, (e0 & k) == 0);
            cmpex(v1, u1, (e1 & j) == 0, (e1 & k) == 0);
            bufsel ^= 1;
        }
        if (k >= 64) {
            bool desc = ((e0 & k) == 0);
            if (desc ? (v0 < v1) : (v0 > v1)) { u64 t = v0; v0 = v1; v1 = t; }
        }
        int jstart = (k >> 1) < 16 ? (k >> 1) : 16;
        for (int j = jstart; j >= 1; j >>= 1) {
            u64 u0 = __shfl_xor_sync(0xFFFFFFFFu, v0, j);
            u64 u1 = __shfl_xor_sync(0xFFFFFFFFu, v1, j);
            bool lower = (lane & j) == 0;
            cmpex(v0, u0, lower, (e0 & k) == 0);
            cmpex(v1, u1, lower, (e1 & k) == 0);
        }
    }
    __syncthreads();   // all smem key reads done before SoA overwrite

    // ---- Phase 3: gather boxes into SoA by sorted rank
    {
        u32 i0 = 0xFFFFFFFFu - (u32)(v0 & 0xFFFFFFFFu);
        u32 i1 = 0xFFFFFFFFu - (u32)(v1 & 0xFFFFFFFFu);
        const float* q = p + (size_t)i0 * 5;
        float l = q[1], t = q[2], r = q[3], bo = q[4];
        sl[e0] = l; st[e0] = t; sr[e0] = r; sb[e0] = bo;
        sha[e0] = 0.5f * ((r - l) * (bo - t));
        q = p + (size_t)i1 * 5;
        l = q[1]; t = q[2]; r = q[3]; bo = q[4];
        sl[e1] = l; st[e1] = t; sr[e1] = r; sb[e1] = bo;
        sha[e1] = 0.5f * ((r - l) * (bo - t));
    }
    if (tid == 0) { s_kept = 0; s_nkept = 0; s_stop = 0; }
    __syncthreads();

    // ---- Phase 4: on-demand chunked greedy (exact). Per 32-box chunk:
    //  A) warp w tests chunk box base+w vs compact kept list + intra-chunk matrix
    //  B) warp 0 resolves greedily (unrolled) and appends kept boxes to the list
    for (int base = 0; base < N_BOX; base += 32) {
        {   // Phase A
            int nk = s_nkept;
            int bc = base + w;
            float lb = sl[bc], tb = st[bc], rb = sr[bc], bb = sb[bc], hb = sha[bc];
            bool sp = false;
            for (int kk = lane; kk < nk; kk += 32) {
                float iw = fminf(rb, kR[kk]) - fmaxf(lb, kL[kk]);
                float ih = fminf(bb, kB2[kk]) - fmaxf(tb, kT[kk]);
                sp |= (fmaxf(iw, 0.0f) * fmaxf(ih, 0.0f) >= hb);
            }
            int ar = base + lane;
            float iw = fminf(rb, sr[ar]) - fmaxf(lb, sl[ar]);
            float ih = fminf(bb, sb[ar]) - fmaxf(tb, st[ar]);
            u32 m   = __ballot_sync(0xFFFFFFFFu, fmaxf(iw, 0.0f) * fmaxf(ih, 0.0f) >= hb);
            u32 spm = __ballot_sync(0xFFFFFFFFu, sp);
            if (lane == 0) { smask[w] = m; sprior[w] = spm; }
        }
        __syncthreads();
        if (w == 0) {   // Phase B+C: all 32 lanes resolve redundantly (broadcast reads)
            int nb  = s_nkept;
            int cnt = s_kept;
            u32 kb = 0;
            #pragma unroll
            for (int a = 0; a < 32; ++a) {
                if (sprior[a] == 0 && (smask[a] & kb) == 0) {
                    kb |= (1u << a);
                    if (cnt < R_OUT && lane == 0) kidx[cnt] = base + a;
                    cnt++;
                }
            }
            bool stop = (cnt >= R_OUT);
            __syncwarp();
            if (!stop && ((kb >> lane) & 1)) {
                int slot = nb + __popc(kb & ((1u << lane) - 1));
                int i = base + lane;
                kL[slot] = sl[i]; kT[slot] = st[i];
                kR[slot] = sr[i]; kB2[slot] = sb[i];
            }
            if (lane == 0) {
                s_kept  = cnt;
                s_nkept = nb + __popc(kb);
                s_stop  = stop;
            }
        }
        __syncthreads();
        if (s_stop) break;
    }

    // ---- Phase 5: output (top, right, bottom) for first R kept, zeros after
    int nk = s_kept; if (nk > R_OUT) nk = R_OUT;
    float* ob = out + (size_t)b * R_OUT * 3;
    if (tid < R_OUT) {
        int s = tid;
        if (s < nk) {
            int i = kidx[s];
            ob[s * 3 + 0] = st[i];
            ob[s * 3 + 1] = sr[i];
            ob[s * 3 + 2] = sb[i];
        } else {
            ob[s * 3 + 0] = 0.0f;
            ob[s * 3 + 1] = 0.0f;
            ob[s * 3 + 2] = 0.0f;
        }
    }
}

extern "C" void kernel_launch(void* const* d_in, const int* in_sizes, int n_in,
                              void* d_out, int out_size) {
    const float* pred = (const float*)d_in[0];
    float* out = (float*)d_out;
    (void)in_sizes; (void)n_in; (void)out_size;
    nms_kernel<<<32, NTHREADS, SMEM_BYTES>>>(pred, out);
}